// round 9
// baseline (speedup 1.0000x reference)
#include <cuda_runtime.h>
#include <cstdint>

// ContactMapGeneration: mean/s_obj + farthest point sampling + gather.
// One cluster (8 CTAs x 512 threads) per batch; 25 scalar point slots per
// thread in registers. Scan uses plain scalar __fadd_rn/__fmul_rn (FFMA-pipe,
// known rt=2) instead of packed f32x2 (suspected slow hidden pipe).
// Tail identical to the best (3485us) kernel: all-threads mbar poll, no hint.

#define CLUSTERSZ 8
#define TPB 512
#define NSLOT 25                 // slot s: idx = t + s*4096; slot 24 guarded
#define STRIDE (CLUSTERSZ * TPB) // 4096 threads per batch
#define MAXNP 2048
#define BIGF 1e10f

typedef unsigned long long u64;

static __device__ __forceinline__ u64 pk2(float lo, float hi) {
    u64 r; asm("mov.b64 %0, {%1,%2};" : "=l"(r) : "f"(lo), "f"(hi)); return r;
}
static __device__ __forceinline__ void upk2(u64 v, float& lo, float& hi) {
    asm("mov.b64 {%0,%1}, %2;" : "=f"(lo), "=f"(hi) : "l"(v));
}

// ---------------- cluster / DSMEM helpers ----------------
static __device__ __forceinline__ unsigned smem_u32(const void* p) {
    return (unsigned)__cvta_generic_to_shared(p);
}
static __device__ __forceinline__ unsigned my_ctarank() {
    unsigned r; asm("mov.u32 %0, %%cluster_ctarank;" : "=r"(r)); return r;
}
static __device__ __forceinline__ void dsmem_st_u64(unsigned addr, unsigned rank, u64 v) {
    asm volatile(
        "{\n\t.reg .b32 r;\n\t"
        "mapa.shared::cluster.u32 r, %0, %1;\n\t"
        "st.shared::cluster.u64 [r], %2;\n\t}"
        :: "r"(addr), "r"(rank), "l"(v) : "memory");
}
static __device__ __forceinline__ void dsmem_st_f32(unsigned addr, unsigned rank, float v) {
    asm volatile(
        "{\n\t.reg .b32 r;\n\t"
        "mapa.shared::cluster.u32 r, %0, %1;\n\t"
        "st.shared::cluster.f32 [r], %2;\n\t}"
        :: "r"(addr), "r"(rank), "f"(v) : "memory");
}
static __device__ __forceinline__ void mbar_arrive_remote(unsigned addr, unsigned rank) {
    asm volatile(
        "{\n\t.reg .b32 r;\n\t"
        "mapa.shared::cluster.u32 r, %0, %1;\n\t"
        "mbarrier.arrive.release.cluster.shared::cluster.b64 _, [r];\n\t}"
        :: "r"(addr), "r"(rank) : "memory");
}
// plain poll (no suspend hint — hint regressed R4 badly)
static __device__ __forceinline__ void mbar_wait(unsigned addr, unsigned parity) {
    asm volatile(
        "{\n\t.reg .pred P;\n"
        "LW%=:\n\t"
        "mbarrier.try_wait.parity.acquire.cluster.shared::cta.b64 P, [%0], %1;\n\t"
        "@!P bra LW%=;\n\t}"
        :: "r"(addr), "r"(parity) : "memory");
}
#define CLUSTER_SYNC() do { \
    asm volatile("barrier.cluster.arrive.aligned;" ::: "memory"); \
    asm volatile("barrier.cluster.wait.aligned;" ::: "memory"); \
} while (0)

// ------------------------------- kernel -------------------------------
__global__ __launch_bounds__(TPB, 1) __cluster_dims__(CLUSTERSZ, 1, 1)
void fps_contact_kernel(const float* __restrict__ mesh,
                        const float* __restrict__ cmap,
                        const int* __restrict__ initf,
                        float* __restrict__ out,
                        int B, int N, int npoint)
{
    // per-warp winners
    __shared__ u64    sh_wkey[16];
    __shared__ float4 sh_wxyz[16];
    // cluster exchange slots, double-buffered, remotely written
    __shared__ u64    sh_ckey[2][CLUSTERSZ];
    __shared__ u64    sh_cxy[2][CLUSTERSZ];
    __shared__ float  sh_cz[2][CLUSTERSZ];
    // stats scratch
    __shared__ float  sh_wsum[16][3];
    __shared__ float  sh_wmax[16];
    __shared__ u64    sh_sxy[CLUSTERSZ];
    __shared__ float  sh_sz[CLUSTERSZ];
    __shared__ float  sh_smax[CLUSTERSZ];
    // selected indices (rank-0 CTA keeps them)
    __shared__ int    sh_fps[MAXNP];
    __shared__ u64    mbar;

    const unsigned rank = my_ctarank();
    const int b    = blockIdx.x / CLUSTERSZ;
    const int tid  = threadIdx.x;
    const int lane = tid & 31;
    const int wid  = tid >> 5;
    const int t    = (int)rank * TPB + tid;        // 0..4095 within batch
    const unsigned mb_addr = smem_u32(&mbar);

    const float* mb = mesh + (size_t)b * N * 3;
    if (npoint > MAXNP) npoint = MAXNP;

    if (tid == 0) {
        asm volatile("mbarrier.init.shared::cta.b64 [%0], %1;"
                     :: "r"(mb_addr), "r"(CLUSTERSZ) : "memory");
    }

    // ---------------- load points into registers (+ local coord table) -------
    float X[NSLOT], Y[NSLOT], Z[NSLOT], PD[NSLOT];
    float4 lq[NSLOT];                              // local mem, winner-indexed only
    float sx = 0.f, sy = 0.f, sz = 0.f;

#pragma unroll
    for (int s = 0; s < NSLOT; s++) {
        const int p = t + s * STRIDE;
        const bool v = (s < NSLOT - 1) || (p < N); // slots 0..23 always valid
        float x = 0.f, y = 0.f, z = 0.f;
        if (v) { x = mb[(size_t)p * 3 + 0]; y = mb[(size_t)p * 3 + 1]; z = mb[(size_t)p * 3 + 2]; }
        X[s] = x; Y[s] = y; Z[s] = z;
        PD[s] = v ? BIGF : 0.0f;
        lq[s] = make_float4(x, y, z, 0.f);
        sx += x; sy += y; sz += z;
    }

    // ---------------- batch mean (centroid) ----------------------------------
#pragma unroll
    for (int off = 16; off; off >>= 1) {
        sx += __shfl_xor_sync(0xffffffffu, sx, off);
        sy += __shfl_xor_sync(0xffffffffu, sy, off);
        sz += __shfl_xor_sync(0xffffffffu, sz, off);
    }
    if (lane == 0) { sh_wsum[wid][0] = sx; sh_wsum[wid][1] = sy; sh_wsum[wid][2] = sz; }
    __syncthreads();
    if (wid == 0) {
        float a = (lane < 16) ? sh_wsum[lane][0] : 0.f;
        float c = (lane < 16) ? sh_wsum[lane][1] : 0.f;
        float d = (lane < 16) ? sh_wsum[lane][2] : 0.f;
#pragma unroll
        for (int off = 8; off; off >>= 1) {
            a += __shfl_xor_sync(0xffffffffu, a, off);
            c += __shfl_xor_sync(0xffffffffu, c, off);
            d += __shfl_xor_sync(0xffffffffu, d, off);
        }
        if (lane < CLUSTERSZ) {
            dsmem_st_u64(smem_u32(&sh_sxy[rank]), lane, pk2(a, c));
            dsmem_st_f32(smem_u32(&sh_sz[rank]),  lane, d);
        }
    }
    CLUSTER_SYNC();   // also publishes mbarrier.init cluster-wide

    float txs = 0.f, tys = 0.f, tzs = 0.f;
#pragma unroll
    for (int r = 0; r < CLUSTERSZ; r++) {
        float a, c; upk2(sh_sxy[r], a, c);
        txs += a; tys += c; tzs += sh_sz[r];
    }
    const float cmx = txs / (float)N, cmy = tys / (float)N, cmz = tzs / (float)N;

    // ---------------- s_obj = sqrt(max ||p - mean||^2) ------------------------
    {
        float md = 0.f;
#pragma unroll
        for (int s = 0; s < NSLOT; s++) {
            float dx = __fadd_rn(X[s], -cmx);
            float dy = __fadd_rn(Y[s], -cmy);
            float dz = __fadd_rn(Z[s], -cmz);
            float ds = __fadd_rn(__fadd_rn(__fmul_rn(dx, dx), __fmul_rn(dy, dy)),
                                 __fmul_rn(dz, dz));
            if (PD[s] != 0.0f) md = fmaxf(md, ds);   // exclude pad slots
        }
#pragma unroll
        for (int off = 16; off; off >>= 1)
            md = fmaxf(md, __shfl_xor_sync(0xffffffffu, md, off));
        if (lane == 0) sh_wmax[wid] = md;
        __syncthreads();
        if (wid == 0) {
            float m = (lane < 16) ? sh_wmax[lane] : 0.f;
#pragma unroll
            for (int off = 8; off; off >>= 1)
                m = fmaxf(m, __shfl_xor_sync(0xffffffffu, m, off));
            if (lane < CLUSTERSZ)
                dsmem_st_f32(smem_u32(&sh_smax[rank]), lane, m);
        }
        CLUSTER_SYNC();
    }
    float maxd = 0.f;
#pragma unroll
    for (int r = 0; r < CLUSTERSZ; r++) maxd = fmaxf(maxd, sh_smax[r]);
    const float s_obj = sqrtf(maxd);

    // ---------------- FPS main loop ------------------------------------------
    int f = initf[b];
    float ncx, ncy, ncz;                           // negated centroid
    {
        ncx = -mb[(size_t)f * 3 + 0];
        ncy = -mb[(size_t)f * 3 + 1];
        ncz = -mb[(size_t)f * 3 + 2];
    }
    unsigned ph = 0;
    int par = 0;

    for (int i = 0; i < npoint; i++) {
        if (rank == 0 && tid == 0) sh_fps[i] = f;
        if (i + 1 == npoint) break;                // last centroid recorded

        // ---- scalar scan (FFMA pipe, rt=2): min-update + two argmax chains --
        float best0 = -1.0f, best1 = -1.0f;
        int   bs0 = 0, bs1 = 1;
#pragma unroll
        for (int s = 0; s < NSLOT; s++) {
            float dx = __fadd_rn(X[s], ncx);       // x + (-cx) == x - cx (exact)
            float dy = __fadd_rn(Y[s], ncy);
            float dz = __fadd_rn(Z[s], ncz);
            float ds = __fadd_rn(__fadd_rn(__fmul_rn(dx, dx), __fmul_rn(dy, dy)),
                                 __fmul_rn(dz, dz));
            float n = fminf(PD[s], ds); PD[s] = n;
            if (s & 1) { if (n > best1) { best1 = n; bs1 = s; } }
            else       { if (n > best0) { best0 = n; bs0 = s; } }
        }
        // merge chains with exact first-index tie-break
        float best; int bs;
        if (best1 > best0 || (best1 == best0 && bs1 < bs0)) { best = best1; bs = bs1; }
        else                                                { best = best0; bs = bs0; }

        const unsigned gidx = (unsigned)t + ((unsigned)bs << 12);
        u64 key = ((u64)__float_as_uint(best) << 32) | (unsigned)(~gidx);

        // ---- warp butterfly: key only ---------------------------------------
#pragma unroll
        for (int off = 16; off; off >>= 1) {
            u64 ok = __shfl_xor_sync(0xffffffffu, key, off);
            if (ok > key) key = ok;
        }
        const unsigned wg = ~(unsigned)key;        // winning global idx in this warp
        if (lane == (int)(wg & 31u)) {
            sh_wkey[wid] = key;
            sh_wxyz[wid] = lq[wg >> 12];           // slot = gidx / 4096
        }
        __syncthreads();

        // ---- threads 0..7: reduce 16 warp winners, push CTA result to CTA[tid]
        if (tid < CLUSTERSZ) {
            u64 bk = sh_wkey[0]; int j = 0;
#pragma unroll
            for (int w = 1; w < 16; w++) {
                u64 k2 = sh_wkey[w];
                if (k2 > bk) { bk = k2; j = w; }
            }
            float4 p = sh_wxyz[j];
            dsmem_st_u64(smem_u32(&sh_ckey[par][rank]), (unsigned)tid, bk);
            dsmem_st_u64(smem_u32(&sh_cxy[par][rank]),  (unsigned)tid, pk2(p.x, p.y));
            dsmem_st_f32(smem_u32(&sh_cz[par][rank]),   (unsigned)tid, p.z);
            mbar_arrive_remote(mb_addr, (unsigned)tid);
        }

        mbar_wait(mb_addr, ph);
        ph ^= 1;

        // ---- all threads reduce the 8 per-CTA candidates identically --------
        u64 bk = sh_ckey[par][0]; int br = 0;
#pragma unroll
        for (int r = 1; r < CLUSTERSZ; r++) {
            u64 k2 = sh_ckey[par][r];
            if (k2 > bk) { bk = k2; br = r; }
        }
        f = (int)(~(unsigned)bk);
        float bx, by; upk2(sh_cxy[par][br], bx, by);
        float bz = sh_cz[par][br];
        ncx = -bx; ncy = -by; ncz = -bz;
        par ^= 1;
    }

    __syncthreads();

    // ---------------- gather + write output (rank-0 CTA per batch) -----------
    if (rank == 0) {
        for (int i = tid; i < npoint; i += TPB) {
            const int idx = sh_fps[i];
            const float x = mb[(size_t)idx * 3 + 0];
            const float y = mb[(size_t)idx * 3 + 1];
            const float z = mb[(size_t)idx * 3 + 2];
            const float c = cmap[(size_t)b * N + idx];
            float4 o = make_float4(c, x / s_obj, y / s_obj, z / s_obj);
            reinterpret_cast<float4*>(out)[(size_t)b * npoint + i] = o;
        }
    }
}

// ------------------------------- launch -------------------------------
extern "C" void kernel_launch(void* const* d_in, const int* in_sizes, int n_in,
                              void* d_out, int out_size) {
    const float* mesh  = (const float*)d_in[0];
    const float* cmap  = (const float*)d_in[1];
    const int*   initf = (const int*)d_in[2];

    const int B = in_sizes[2];
    const int N = in_sizes[0] / (3 * B);
    const int npoint = out_size / (4 * B);   // out = [B, npoint, 4] float32

    dim3 grid(B * CLUSTERSZ);
    dim3 block(TPB);
    fps_contact_kernel<<<grid, block>>>(mesh, cmap, initf, (float*)d_out,
                                        B, N, npoint);
}